// round 10
// baseline (speedup 1.0000x reference)
#include <cuda_runtime.h>
#include <cuda_bf16.h>
#include <math_constants.h>
#include <cstdint>

// Problem constants
#define BB   128
#define NN   196
#define DD   768
#define NTOK (BB * NN)      // 25088
#define EPSF 1e-6f
#define EMAX3 1024          // per-quadrant-CTA edge-list capacity

// ---------------- static device scratch (no allocations allowed) -------------
__device__ float    g_sim[(size_t)BB * NN * NN];   // fallback only (~19.7 MB)
__device__ float    g_w[NTOK];
__device__ int      g_members[NTOK];
__device__ int      g_goff[BB * (NN + 1)];
__device__ int      g_edge_cnt[BB * 3];
__device__ int      g_edges[BB * 3 * EMAX3];

// ---------------- kernel 1: cosine similarity via tf32 mma.sync --------------
// 3 CTAs per batch: (0,0) diag, (0,1) offdiag (+mirror via smem transpose),
// (1,1) diag. 8 warps (2x4), warp tile 64x32, K-chunk 16, reg-prefetch +
// double-buffered smem, ONE barrier per chunk. Row norms accumulated in the
// fill loop, applied at epilogue. Atom-level trimming: warps skip m/n atoms
// beyond NN (warp-uniform bounds). Edge detection fused; per-CTA edge lists.
#define KC   16
#define NCH  (DD / KC)     // 48
#define SSTR 20            // smem row stride (floats): conflict-free frag LDS

__device__ __forceinline__ float to_tf32(float x) {
    float r; asm("cvt.rna.tf32.f32 %0, %1;" : "=f"(r) : "f"(x)); return r;
}
__device__ __forceinline__ void mma_tf32(float (&d)[4], const unsigned (&a)[4],
                                         const unsigned (&b)[2]) {
    asm volatile("mma.sync.aligned.m16n8k8.row.col.f32.tf32.tf32.f32 "
                 "{%0,%1,%2,%3}, {%4,%5,%6,%7}, {%8,%9}, {%0,%1,%2,%3};\n"
                 : "+f"(d[0]), "+f"(d[1]), "+f"(d[2]), "+f"(d[3])
                 : "r"(a[0]), "r"(a[1]), "r"(a[2]), "r"(a[3]),
                   "r"(b[0]), "r"(b[1]));
}
__device__ __forceinline__ void rec_edge(int slot_base, int i, int j) {
    int slot = atomicAdd(&g_edge_cnt[slot_base], 1);
    if (slot < EMAX3) g_edges[slot_base * EMAX3 + slot] = (i << 8) | j;
}

__global__ void __launch_bounds__(256)
sim_kernel(const float* __restrict__ tok, float* __restrict__ sim_out_arg) {
    __shared__ float rnA[128], rnB[128];
    __shared__ __align__(16) float As[2][128 * SSTR];
    __shared__ __align__(16) float Bs[2][128 * SSTR];

    float* sim_out = sim_out_arg ? sim_out_arg : g_sim;
    int b  = blockIdx.y;
    int bx = blockIdx.x;                 // 0:(0,0)  1:(0,1)+mirror  2:(1,1)
    int ti = (bx == 2) ? 1 : 0;
    int tj = (bx >= 1) ? 1 : 0;
    int i0 = ti * 128, j0 = tj * 128;
    bool diag   = (ti == tj);
    bool mirror = (bx == 1);
    int tid  = threadIdx.x;
    int lane = tid & 31, warp = tid >> 5;
    int wm = warp >> 2, wn = warp & 3;
    int g4 = lane >> 2, t4 = lane & 3;
    int eslot = b * 3 + bx;

    if (tid == 0) g_edge_cnt[eslot] = 0;   // own counter; barriers below order it

    // warp-uniform atom trimming bounds
    int mrem = NN - i0 - wm * 64;
    int nrem = NN - j0 - wn * 32;
    int ma_cnt = mrem <= 0 ? 0 : (mrem + 15) >> 4; if (ma_cnt > 4) ma_cnt = 4;
    int na_cnt = nrem <= 0 ? 0 : (nrem + 7) >> 3;  if (na_cnt > 4) na_cnt = 4;

    float acc[4][4][4];
    #pragma unroll
    for (int ma = 0; ma < 4; ma++)
        #pragma unroll
        for (int na = 0; na < 4; na++)
            #pragma unroll
            for (int q = 0; q < 4; q++) acc[ma][na][q] = 0.f;

    const float* tokb = tok + (size_t)b * NN * DD;
    int frow0 = (tid >> 2);
    int fcol  = (tid & 3) * 4;

    float ssa[2] = {0.f, 0.f}, ssb[2] = {0.f, 0.f};

    float4 pa[2], pb[2];
    #pragma unroll
    for (int it = 0; it < 2; it++) {
        int row = it * 64 + frow0;
        pa[it] = (i0 + row < NN) ? *(const float4*)(tokb + (size_t)(i0 + row) * DD + fcol)
                                 : make_float4(0.f, 0.f, 0.f, 0.f);
        if (!diag)
            pb[it] = (j0 + row < NN) ? *(const float4*)(tokb + (size_t)(j0 + row) * DD + fcol)
                                     : make_float4(0.f, 0.f, 0.f, 0.f);
    }

    for (int c = 0; c < NCH; c++) {
        float* A = As[c & 1];
        float* Bm = diag ? As[c & 1] : Bs[c & 1];

        #pragma unroll
        for (int it = 0; it < 2; it++) {
            int row = it * 64 + frow0;
            float4 v = pa[it];
            ssa[it] += v.x * v.x + v.y * v.y + v.z * v.z + v.w * v.w;
            *(float4*)&A[row * SSTR + fcol] =
                make_float4(to_tf32(v.x), to_tf32(v.y), to_tf32(v.z), to_tf32(v.w));
            if (!diag) {
                float4 w = pb[it];
                ssb[it] += w.x * w.x + w.y * w.y + w.z * w.z + w.w * w.w;
                *(float4*)&Bs[c & 1][row * SSTR + fcol] =
                    make_float4(to_tf32(w.x), to_tf32(w.y), to_tf32(w.z), to_tf32(w.w));
            }
        }
        __syncthreads();

        if (c + 1 < NCH) {
            int koff = (c + 1) * KC + fcol;
            #pragma unroll
            for (int it = 0; it < 2; it++) {
                int row = it * 64 + frow0;
                pa[it] = (i0 + row < NN) ? *(const float4*)(tokb + (size_t)(i0 + row) * DD + koff)
                                         : make_float4(0.f, 0.f, 0.f, 0.f);
                if (!diag)
                    pb[it] = (j0 + row < NN) ? *(const float4*)(tokb + (size_t)(j0 + row) * DD + koff)
                                             : make_float4(0.f, 0.f, 0.f, 0.f);
            }
        }

        #pragma unroll
        for (int ks = 0; ks < 2; ks++) {
            int kb = ks * 8 + t4;
            unsigned afr[4][4];
            #pragma unroll
            for (int ma = 0; ma < 4; ma++) {
                if (ma >= ma_cnt) break;
                int r = wm * 64 + ma * 16 + g4;
                afr[ma][0] = __float_as_uint(A[r * SSTR + kb]);
                afr[ma][1] = __float_as_uint(A[(r + 8) * SSTR + kb]);
                afr[ma][2] = __float_as_uint(A[r * SSTR + kb + 4]);
                afr[ma][3] = __float_as_uint(A[(r + 8) * SSTR + kb + 4]);
            }
            unsigned bfr[4][2];
            #pragma unroll
            for (int na = 0; na < 4; na++) {
                if (na >= na_cnt) break;
                int cidx = wn * 32 + na * 8 + g4;
                bfr[na][0] = __float_as_uint(Bm[cidx * SSTR + kb]);
                bfr[na][1] = __float_as_uint(Bm[cidx * SSTR + kb + 4]);
            }
            #pragma unroll
            for (int ma = 0; ma < 4; ma++) {
                if (ma >= ma_cnt) break;
                #pragma unroll
                for (int na = 0; na < 4; na++) {
                    if (na >= na_cnt) break;
                    mma_tf32(acc[ma][na], afr[ma], bfr[na]);
                }
            }
        }
        // no trailing barrier: next fill writes the OTHER buffer; the reuse
        // hazard (c+2 vs compute c) is fenced by the next iteration's barrier.
    }

    // ---- reduce per-row sum of squares -> reciprocal norms in smem ----
    #pragma unroll
    for (int it = 0; it < 2; it++) {
        float s = ssa[it];
        s += __shfl_xor_sync(0xffffffffu, s, 1);
        s += __shfl_xor_sync(0xffffffffu, s, 2);
        if (t4 == 0) rnA[it * 64 + frow0] = 1.0f / fmaxf(sqrtf(s), 1e-12f);
        if (!diag) {
            float t = ssb[it];
            t += __shfl_xor_sync(0xffffffffu, t, 1);
            t += __shfl_xor_sync(0xffffffffu, t, 2);
            if (t4 == 0) rnB[it * 64 + frow0] = 1.0f / fmaxf(sqrtf(t), 1e-12f);
        }
    }
    __syncthreads();
    const float* rnBp = diag ? rnA : rnB;

    // ---- epilogue 1: this quadrant's tile (coalesced float2, scaled) ----
    #pragma unroll
    for (int ma = 0; ma < 4; ma++) {
        #pragma unroll
        for (int na = 0; na < 4; na++) {
            int lj = wn * 32 + na * 8 + 2 * t4;
            int gj = j0 + lj;
            if (gj >= NN) continue;
            float rb0 = rnBp[lj], rb1 = rnBp[lj + 1];
            #pragma unroll
            for (int h = 0; h < 2; h++) {
                int li = wm * 64 + ma * 16 + g4 + h * 8;
                int gi = i0 + li;
                if (gi >= NN) continue;
                float ra = rnA[li];
                float v0 = acc[ma][na][h * 2 + 0] * ra * rb0;
                float v1 = acc[ma][na][h * 2 + 1] * ra * rb1;
                if (diag) {
                    if (gi == gj)     v0 = 0.f;
                    if (gi == gj + 1) v1 = 0.f;
                }
                if (v0 > 0.9f) rec_edge(eslot, gi, gj);
                if (v1 > 0.9f && gj + 1 < NN) rec_edge(eslot, gi, gj + 1);
                *(float2*)&sim_out[((size_t)b * NN + gi) * NN + gj] = make_float2(v0, v1);
            }
        }
    }

    // ---- epilogue 2: mirror (1,0) via smem transpose (off-diag CTA only) ----
    if (mirror) {
        float* S = &As[0][0];            // 32 x 132 staging
        #pragma unroll
        for (int cb = 0; cb < 3; cb++) {   // local col chunks; cb=3 all OOB
            __syncthreads();
            if (wn == cb) {
                #pragma unroll
                for (int ma = 0; ma < 4; ma++)
                    #pragma unroll
                    for (int na = 0; na < 4; na++)
                        #pragma unroll
                        for (int q = 0; q < 4; q++) {
                            int jc = na * 8 + 2 * t4 + (q & 1);
                            int il = wm * 64 + ma * 16 + g4 + 8 * (q >> 1);
                            S[jc * 132 + il] = acc[ma][na][q] * rnA[il] * rnBp[cb * 32 + jc];
                        }
            }
            __syncthreads();
            #pragma unroll
            for (int it = 0; it < 4; it++) {
                int jc = it * 8 + (tid >> 5);
                int gj = 128 + cb * 32 + jc;       // mirror row
                if (gj >= NN) continue;
                int i = (tid & 31) * 4;
                float4 v = *(float4*)&S[jc * 132 + i];
                if (v.x > 0.9f) rec_edge(eslot, gj, i + 0);
                if (v.y > 0.9f) rec_edge(eslot, gj, i + 1);
                if (v.z > 0.9f) rec_edge(eslot, gj, i + 2);
                if (v.w > 0.9f) rec_edge(eslot, gj, i + 3);
                *(float4*)&sim_out[((size_t)b * NN + gj) * NN + i] = v;
            }
        }
    }
}

// ---------------- kernel 2: grouping (fused gmax + importance) ---------------
__global__ void __launch_bounds__(256, 1)
group_kernel(const float* __restrict__ m, const float* __restrict__ s,
             const float* __restrict__ sim_in_arg,
             float* out_imp, float* out_gids) {
    int b = blockIdx.x, tid = threadIdx.x;
    const float* sim_in = sim_in_arg ? sim_in_arg : g_sim;
    __shared__ unsigned adj[NN][8];
    __shared__ float simp[NN];
    __shared__ int   sgid[NN];
    __shared__ float denom[NN];
    __shared__ int   cnt[NN];
    __shared__ int   off[NN + 1];
    __shared__ int   cur[NN];
    __shared__ float lo[256], hi[256];
    __shared__ float wr0[8], wr1[8];
    __shared__ unsigned assigned[8], reach[8], nxt[8];
    __shared__ int s_changed, s_ng, s_any;

    // ---- global max of motion / saliency (deterministic per-CTA scan) ----
    float mx0 = 0.f, mx1 = 0.f;
    for (int i = tid; i < NTOK; i += 256) {
        mx0 = fmaxf(mx0, m[i]);
        mx1 = fmaxf(mx1, s[i]);
    }
    #pragma unroll
    for (int o = 16; o; o >>= 1) {
        mx0 = fmaxf(mx0, __shfl_xor_sync(0xffffffffu, mx0, o));
        mx1 = fmaxf(mx1, __shfl_xor_sync(0xffffffffu, mx1, o));
    }
    int lane = tid & 31, warp = tid >> 5;
    if (lane == 0) { wr0[warp] = mx0; wr1[warp] = mx1; }
    __syncthreads();
    float gm0 = wr0[0], gm1 = wr1[0];
    #pragma unroll
    for (int w = 1; w < 8; w++) { gm0 = fmaxf(gm0, wr0[w]); gm1 = fmaxf(gm1, wr1[w]); }

    // ---- importance for this batch ----
    bool valid = (tid < NN);
    float v = 0.f;
    if (valid) {
        float mn = m[b * NN + tid] / (gm0 + EPSF);
        float sn = s[b * NN + tid] / (gm1 + EPSF);
        v = 0.5f * mn + 0.5f * sn;
    }
    lo[tid] = valid ? v :  CUDART_INF_F;
    hi[tid] = valid ? v : -CUDART_INF_F;
    __syncthreads();
    for (int o = 128; o; o >>= 1) {
        if (tid < o) { lo[tid] = fminf(lo[tid], lo[tid + o]); hi[tid] = fmaxf(hi[tid], hi[tid + o]); }
        __syncthreads();
    }
    float l = lo[0], h = hi[0];
    if (valid) {
        float r = (v - l) / (h - l + EPSF);
        simp[tid] = r;
        if (out_imp) out_imp[b * NN + tid] = r;
    }
    for (int i = tid; i < NN; i += 256) { cnt[i] = 0; denom[i] = EPSF; }
    if (tid < 8) assigned[tid] = 0u;
    if (tid == 0) { s_ng = 0; s_any = 0; }
    __syncthreads();

    // ---- adjacency from per-quadrant edge lists ----
    int e0 = g_edge_cnt[b * 3 + 0];
    int e1 = g_edge_cnt[b * 3 + 1];
    int e2 = g_edge_cnt[b * 3 + 2];
    int etot = e0 + e1 + e2;
    bool overflow = (e0 > EMAX3) || (e1 > EMAX3) || (e2 > EMAX3);

    if (etot == 0) {
        for (int i = tid; i < NN; i += 256) sgid[i] = i;
        if (tid == 0) s_ng = NN;
        __syncthreads();
    } else {
        for (int i = tid; i < NN * 8; i += 256) (&adj[0][0])[i] = 0u;
        __syncthreads();
        if (!overflow) {
            #pragma unroll
            for (int q = 0; q < 3; q++) {
                int ec = (q == 0) ? e0 : (q == 1) ? e1 : e2;
                const int* el = &g_edges[(b * 3 + q) * EMAX3];
                for (int e = tid; e < ec; e += 256) {
                    int pk = el[e];
                    int i = pk >> 8, j = pk & 255;
                    if (j < NN && (1.0f - simp[i]) > 0.5f) {
                        atomicOr(&adj[i][j >> 5], 1u << (j & 31));
                        s_any = 1;
                    }
                }
            }
        } else {
            const float* simb = sim_in + (size_t)b * NN * NN;
            for (int idx = tid; idx < NN * NN; idx += 256) {
                int i = idx / NN, j = idx - i * NN;
                float sv = simb[idx];
                if (sv > 0.9f && (1.0f - simp[i]) > 0.5f) {
                    atomicOr(&adj[i][j >> 5], 1u << (j & 31));
                    s_any = 1;
                }
            }
        }
        __syncthreads();

        if (s_any == 0) {
            for (int i = tid; i < NN; i += 256) sgid[i] = i;
            if (tid == 0) s_ng = NN;
            __syncthreads();
        } else {
            for (int r = 0; r < NN; r++) {
                if ((assigned[r >> 5] >> (r & 31)) & 1u) continue;
                if (tid < 8) reach[tid] = (tid == (r >> 5)) ? (1u << (r & 31)) : 0u;
                __syncthreads();
                while (true) {
                    if (tid < 8) nxt[tid] = 0u;
                    if (tid == 0) s_changed = 0;
                    __syncthreads();
                    for (int i = tid; i < NN; i += 256) {
                        if ((reach[i >> 5] >> (i & 31)) & 1u) {
                            #pragma unroll
                            for (int w = 0; w < 7; w++) {
                                unsigned vv = adj[i][w];
                                if (vv) atomicOr(&nxt[w], vv);
                            }
                        }
                    }
                    __syncthreads();
                    if (tid < 8) {
                        unsigned nv = reach[tid] | (nxt[tid] & ~assigned[tid]);
                        if (nv != reach[tid]) s_changed = 1;
                        nxt[tid] = nv;
                    }
                    __syncthreads();
                    if (tid < 8) reach[tid] = nxt[tid];
                    __syncthreads();
                    if (!s_changed) break;
                }
                int gid = s_ng;
                for (int i = tid; i < NN; i += 256)
                    if ((reach[i >> 5] >> (i & 31)) & 1u) sgid[i] = gid;
                if (tid < 8) assigned[tid] |= reach[tid];
                __syncthreads();
                if (tid == 0) s_ng = gid + 1;
                __syncthreads();
            }
        }
    }

    // ---- weights + CSR ----
    for (int i = tid; i < NN; i += 256) atomicAdd(&denom[sgid[i]], simp[i]);
    __syncthreads();
    for (int i = tid; i < NN; i += 256) {
        g_w[b * NN + i] = simp[i] / denom[sgid[i]];
        if (out_gids) out_gids[b * NN + i] = (float)sgid[i];
        atomicAdd(&cnt[sgid[i]], 1);
    }
    __syncthreads();
    if (tid == 0) {
        off[0] = 0;
        for (int g = 0; g < NN; g++) off[g + 1] = off[g] + cnt[g];
    }
    __syncthreads();
    for (int g = tid; g < NN; g += 256) cur[g] = off[g];
    for (int g = tid; g < NN + 1; g += 256) g_goff[b * (NN + 1) + g] = off[g];
    __syncthreads();
    for (int i = tid; i < NN; i += 256) {
        int g = sgid[i];
        int pos = atomicAdd(&cur[g], 1);
        g_members[b * NN + pos] = i;
    }
}

// ---------------- kernel 3: merged tokens (CSR gather, float4) ----------------
__global__ void __launch_bounds__(192)
merge_kernel(const float* __restrict__ tok, float* __restrict__ out) {
    int b = blockIdx.y, g = blockIdx.x, tid = threadIdx.x;
    int o0 = g_goff[b * (NN + 1) + g];
    int o1 = g_goff[b * (NN + 1) + g + 1];
    float4 a = make_float4(0.f, 0.f, 0.f, 0.f);
    const float4* tokb = (const float4*)(tok + (size_t)b * NN * DD);
    for (int k = o0; k < o1; k++) {
        int i = g_members[b * NN + k];
        float wv = g_w[b * NN + i];
        float4 v = tokb[(size_t)i * (DD / 4) + tid];
        a.x += v.x * wv; a.y += v.y * wv; a.z += v.z * wv; a.w += v.w * wv;
    }
    ((float4*)out)[((size_t)b * NN + g) * (DD / 4) + tid] = a;
}

// ---------------- launch ------------------------------------------------------
extern "C" void kernel_launch(void* const* d_in, const int* in_sizes, int n_in,
                              void* d_out, int out_size) {
    const float* tokens = (const float*)d_in[0];
    const float* motion = (const float*)d_in[1];
    const float* sal    = (const float*)d_in[2];
    float* out = (float*)d_out;

    const long long SZ_M = (long long)BB * NN * DD;   // 19267584
    const long long SZ_S = (long long)BB * NN * NN;   //  4917248
    const long long SZ_I = (long long)BB * NN;        //    25088
    long long osz = (long long)out_size;

    float* out_sim  = (osz >= SZ_M + SZ_S)            ? out + SZ_M               : nullptr;
    float* out_imp  = (osz >= SZ_M + SZ_S + SZ_I)     ? out + SZ_M + SZ_S        : nullptr;
    float* out_gids = (osz >= SZ_M + SZ_S + 2 * SZ_I) ? out + SZ_M + SZ_S + SZ_I : nullptr;

    sim_kernel<<<dim3(3, BB), 256>>>(tokens, out_sim);
    group_kernel<<<BB, 256>>>(motion, sal, out_sim, out_imp, out_gids);
    merge_kernel<<<dim3(NN, BB), 192>>>(tokens, out);
}

// round 11
// speedup vs baseline: 1.4599x; 1.4599x over previous
#include <cuda_runtime.h>
#include <cuda_bf16.h>
#include <math_constants.h>
#include <cstdint>

// Problem constants
#define BB   128
#define NN   196
#define DD   768
#define NTOK (BB * NN)      // 25088
#define EPSF 1e-6f
#define EMAX3 1024          // per-quadrant-CTA edge-list capacity

// ---------------- static device scratch (no allocations allowed) -------------
__device__ float    g_sim[(size_t)BB * NN * NN];   // fallback only (~19.7 MB)
__device__ float    g_w[NTOK];
__device__ int      g_members[NTOK];
__device__ int      g_goff[BB * (NN + 1)];
__device__ int      g_edge_cnt[BB * 3];
__device__ int      g_edges[BB * 3 * EMAX3];

// ---------------- kernel 1: cosine similarity via tf32 mma.sync --------------
// 3 CTAs per batch: (0,0) diag, (0,1) offdiag (+mirror via smem transpose),
// (1,1) diag. 8 warps (2x4), warp tile 64x32, K-chunk 16, reg-prefetch +
// double-buffered smem, ONE barrier per chunk. Fully unrolled 4x4 atoms (NO
// runtime trimming -- round-10 lesson: dynamic bounds cost 2x). Row norms
// accumulated in the fill loop, applied at epilogue. Edge detection fused;
// per-quadrant-CTA edge lists (self-initialized, no init kernel).
#define KC   16
#define NCH  (DD / KC)     // 48
#define SSTR 20            // smem row stride (floats): conflict-free frag LDS

__device__ __forceinline__ float to_tf32(float x) {
    float r; asm("cvt.rna.tf32.f32 %0, %1;" : "=f"(r) : "f"(x)); return r;
}
__device__ __forceinline__ void mma_tf32(float (&d)[4], const unsigned (&a)[4],
                                         const unsigned (&b)[2]) {
    asm volatile("mma.sync.aligned.m16n8k8.row.col.f32.tf32.tf32.f32 "
                 "{%0,%1,%2,%3}, {%4,%5,%6,%7}, {%8,%9}, {%0,%1,%2,%3};\n"
                 : "+f"(d[0]), "+f"(d[1]), "+f"(d[2]), "+f"(d[3])
                 : "r"(a[0]), "r"(a[1]), "r"(a[2]), "r"(a[3]),
                   "r"(b[0]), "r"(b[1]));
}
__device__ __forceinline__ void rec_edge(int slot_base, int i, int j) {
    int slot = atomicAdd(&g_edge_cnt[slot_base], 1);
    if (slot < EMAX3) g_edges[slot_base * EMAX3 + slot] = (i << 8) | j;
}

__global__ void __launch_bounds__(256)
sim_kernel(const float* __restrict__ tok, float* __restrict__ sim_out_arg) {
    __shared__ float rnA[128], rnB[128];
    __shared__ __align__(16) float As[2][128 * SSTR];
    __shared__ __align__(16) float Bs[2][128 * SSTR];

    float* sim_out = sim_out_arg ? sim_out_arg : g_sim;
    int b  = blockIdx.y;
    int bx = blockIdx.x;                 // 0:(0,0)  1:(0,1)+mirror  2:(1,1)
    int ti = (bx == 2) ? 1 : 0;
    int tj = (bx >= 1) ? 1 : 0;
    int i0 = ti * 128, j0 = tj * 128;
    bool diag   = (ti == tj);
    bool mirror = (bx == 1);
    int tid  = threadIdx.x;
    int lane = tid & 31, warp = tid >> 5;
    int wm = warp >> 2, wn = warp & 3;
    int g4 = lane >> 2, t4 = lane & 3;
    int eslot = b * 3 + bx;

    if (tid == 0) g_edge_cnt[eslot] = 0;   // own counter; epilogue barriers order it

    float acc[4][4][4];
    #pragma unroll
    for (int ma = 0; ma < 4; ma++)
        #pragma unroll
        for (int na = 0; na < 4; na++)
            #pragma unroll
            for (int q = 0; q < 4; q++) acc[ma][na][q] = 0.f;

    const float* tokb = tok + (size_t)b * NN * DD;
    int frow0 = (tid >> 2);
    int fcol  = (tid & 3) * 4;

    float ssa[2] = {0.f, 0.f}, ssb[2] = {0.f, 0.f};

    float4 pa[2], pb[2];
    #pragma unroll
    for (int it = 0; it < 2; it++) {
        int row = it * 64 + frow0;
        pa[it] = (i0 + row < NN) ? *(const float4*)(tokb + (size_t)(i0 + row) * DD + fcol)
                                 : make_float4(0.f, 0.f, 0.f, 0.f);
        if (!diag)
            pb[it] = (j0 + row < NN) ? *(const float4*)(tokb + (size_t)(j0 + row) * DD + fcol)
                                     : make_float4(0.f, 0.f, 0.f, 0.f);
    }

    for (int c = 0; c < NCH; c++) {
        float* A = As[c & 1];
        float* Bm = diag ? As[c & 1] : Bs[c & 1];

        #pragma unroll
        for (int it = 0; it < 2; it++) {
            int row = it * 64 + frow0;
            float4 v = pa[it];
            ssa[it] += v.x * v.x + v.y * v.y + v.z * v.z + v.w * v.w;
            *(float4*)&A[row * SSTR + fcol] =
                make_float4(to_tf32(v.x), to_tf32(v.y), to_tf32(v.z), to_tf32(v.w));
            if (!diag) {
                float4 w = pb[it];
                ssb[it] += w.x * w.x + w.y * w.y + w.z * w.z + w.w * w.w;
                *(float4*)&Bs[c & 1][row * SSTR + fcol] =
                    make_float4(to_tf32(w.x), to_tf32(w.y), to_tf32(w.z), to_tf32(w.w));
            }
        }
        __syncthreads();

        if (c + 1 < NCH) {
            int koff = (c + 1) * KC + fcol;
            #pragma unroll
            for (int it = 0; it < 2; it++) {
                int row = it * 64 + frow0;
                pa[it] = (i0 + row < NN) ? *(const float4*)(tokb + (size_t)(i0 + row) * DD + koff)
                                         : make_float4(0.f, 0.f, 0.f, 0.f);
                if (!diag)
                    pb[it] = (j0 + row < NN) ? *(const float4*)(tokb + (size_t)(j0 + row) * DD + koff)
                                             : make_float4(0.f, 0.f, 0.f, 0.f);
            }
        }

        #pragma unroll
        for (int ks = 0; ks < 2; ks++) {
            int kb = ks * 8 + t4;
            unsigned afr[4][4];
            #pragma unroll
            for (int ma = 0; ma < 4; ma++) {
                int r = wm * 64 + ma * 16 + g4;
                afr[ma][0] = __float_as_uint(A[r * SSTR + kb]);
                afr[ma][1] = __float_as_uint(A[(r + 8) * SSTR + kb]);
                afr[ma][2] = __float_as_uint(A[r * SSTR + kb + 4]);
                afr[ma][3] = __float_as_uint(A[(r + 8) * SSTR + kb + 4]);
            }
            unsigned bfr[4][2];
            #pragma unroll
            for (int na = 0; na < 4; na++) {
                int cidx = wn * 32 + na * 8 + g4;
                bfr[na][0] = __float_as_uint(Bm[cidx * SSTR + kb]);
                bfr[na][1] = __float_as_uint(Bm[cidx * SSTR + kb + 4]);
            }
            #pragma unroll
            for (int ma = 0; ma < 4; ma++)
                #pragma unroll
                for (int na = 0; na < 4; na++)
                    mma_tf32(acc[ma][na], afr[ma], bfr[na]);
        }
        // no trailing barrier: next fill writes the OTHER buffer; the reuse
        // hazard (c+2 vs compute c) is fenced by the next iteration's barrier.
    }

    // ---- reduce per-row sum of squares -> reciprocal norms in smem ----
    #pragma unroll
    for (int it = 0; it < 2; it++) {
        float s = ssa[it];
        s += __shfl_xor_sync(0xffffffffu, s, 1);
        s += __shfl_xor_sync(0xffffffffu, s, 2);
        if (t4 == 0) rnA[it * 64 + frow0] = 1.0f / fmaxf(sqrtf(s), 1e-12f);
        if (!diag) {
            float t = ssb[it];
            t += __shfl_xor_sync(0xffffffffu, t, 1);
            t += __shfl_xor_sync(0xffffffffu, t, 2);
            if (t4 == 0) rnB[it * 64 + frow0] = 1.0f / fmaxf(sqrtf(t), 1e-12f);
        }
    }
    __syncthreads();
    const float* rnBp = diag ? rnA : rnB;

    // ---- epilogue 1: this quadrant's tile (coalesced float2, scaled) ----
    #pragma unroll
    for (int ma = 0; ma < 4; ma++) {
        #pragma unroll
        for (int na = 0; na < 4; na++) {
            int lj = wn * 32 + na * 8 + 2 * t4;
            int gj = j0 + lj;
            if (gj >= NN) continue;
            float rb0 = rnBp[lj], rb1 = rnBp[lj + 1];
            #pragma unroll
            for (int h = 0; h < 2; h++) {
                int li = wm * 64 + ma * 16 + g4 + h * 8;
                int gi = i0 + li;
                if (gi >= NN) continue;
                float ra = rnA[li];
                float v0 = acc[ma][na][h * 2 + 0] * ra * rb0;
                float v1 = acc[ma][na][h * 2 + 1] * ra * rb1;
                if (diag) {
                    if (gi == gj)     v0 = 0.f;
                    if (gi == gj + 1) v1 = 0.f;
                }
                if (v0 > 0.9f) rec_edge(eslot, gi, gj);
                if (v1 > 0.9f && gj + 1 < NN) rec_edge(eslot, gi, gj + 1);
                *(float2*)&sim_out[((size_t)b * NN + gi) * NN + gj] = make_float2(v0, v1);
            }
        }
    }

    // ---- epilogue 2: mirror (1,0) via smem transpose (off-diag CTA only) ----
    if (mirror) {
        float* S = &As[0][0];            // 32 x 132 staging
        #pragma unroll
        for (int cb = 0; cb < 3; cb++) {   // local col chunks; cb=3 all OOB
            __syncthreads();
            if (wn == cb) {
                #pragma unroll
                for (int ma = 0; ma < 4; ma++)
                    #pragma unroll
                    for (int na = 0; na < 4; na++)
                        #pragma unroll
                        for (int q = 0; q < 4; q++) {
                            int jc = na * 8 + 2 * t4 + (q & 1);
                            int il = wm * 64 + ma * 16 + g4 + 8 * (q >> 1);
                            S[jc * 132 + il] = acc[ma][na][q] * rnA[il] * rnBp[cb * 32 + jc];
                        }
            }
            __syncthreads();
            #pragma unroll
            for (int it = 0; it < 4; it++) {
                int jc = it * 8 + (tid >> 5);
                int gj = 128 + cb * 32 + jc;       // mirror row
                if (gj >= NN) continue;
                int i = (tid & 31) * 4;
                float4 v = *(float4*)&S[jc * 132 + i];
                if (v.x > 0.9f) rec_edge(eslot, gj, i + 0);
                if (v.y > 0.9f) rec_edge(eslot, gj, i + 1);
                if (v.z > 0.9f) rec_edge(eslot, gj, i + 2);
                if (v.w > 0.9f) rec_edge(eslot, gj, i + 3);
                *(float4*)&sim_out[((size_t)b * NN + gj) * NN + i] = v;
            }
        }
    }
}

// ---------------- kernel 2: grouping (fused gmax + importance) ---------------
__global__ void __launch_bounds__(256, 1)
group_kernel(const float* __restrict__ m, const float* __restrict__ s,
             const float* __restrict__ sim_in_arg,
             float* out_imp, float* out_gids) {
    int b = blockIdx.x, tid = threadIdx.x;
    const float* sim_in = sim_in_arg ? sim_in_arg : g_sim;
    __shared__ unsigned adj[NN][8];
    __shared__ float simp[NN];
    __shared__ int   sgid[NN];
    __shared__ float denom[NN];
    __shared__ int   cnt[NN];
    __shared__ int   off[NN + 1];
    __shared__ int   cur[NN];
    __shared__ float lo[256], hi[256];
    __shared__ float wr0[8], wr1[8];
    __shared__ unsigned assigned[8], reach[8], nxt[8];
    __shared__ int s_changed, s_ng, s_any;

    // ---- global max of motion / saliency (deterministic per-CTA scan) ----
    float mx0 = 0.f, mx1 = 0.f;
    for (int i = tid; i < NTOK; i += 256) {
        mx0 = fmaxf(mx0, m[i]);
        mx1 = fmaxf(mx1, s[i]);
    }
    #pragma unroll
    for (int o = 16; o; o >>= 1) {
        mx0 = fmaxf(mx0, __shfl_xor_sync(0xffffffffu, mx0, o));
        mx1 = fmaxf(mx1, __shfl_xor_sync(0xffffffffu, mx1, o));
    }
    int lane = tid & 31, warp = tid >> 5;
    if (lane == 0) { wr0[warp] = mx0; wr1[warp] = mx1; }
    __syncthreads();
    float gm0 = wr0[0], gm1 = wr1[0];
    #pragma unroll
    for (int w = 1; w < 8; w++) { gm0 = fmaxf(gm0, wr0[w]); gm1 = fmaxf(gm1, wr1[w]); }

    // ---- importance for this batch ----
    bool valid = (tid < NN);
    float v = 0.f;
    if (valid) {
        float mn = m[b * NN + tid] / (gm0 + EPSF);
        float sn = s[b * NN + tid] / (gm1 + EPSF);
        v = 0.5f * mn + 0.5f * sn;
    }
    lo[tid] = valid ? v :  CUDART_INF_F;
    hi[tid] = valid ? v : -CUDART_INF_F;
    __syncthreads();
    for (int o = 128; o; o >>= 1) {
        if (tid < o) { lo[tid] = fminf(lo[tid], lo[tid + o]); hi[tid] = fmaxf(hi[tid], hi[tid + o]); }
        __syncthreads();
    }
    float l = lo[0], h = hi[0];
    if (valid) {
        float r = (v - l) / (h - l + EPSF);
        simp[tid] = r;
        if (out_imp) out_imp[b * NN + tid] = r;
    }
    for (int i = tid; i < NN; i += 256) { cnt[i] = 0; denom[i] = EPSF; }
    if (tid < 8) assigned[tid] = 0u;
    if (tid == 0) { s_ng = 0; s_any = 0; }
    __syncthreads();

    // ---- adjacency from per-quadrant edge lists ----
    int e0 = g_edge_cnt[b * 3 + 0];
    int e1 = g_edge_cnt[b * 3 + 1];
    int e2 = g_edge_cnt[b * 3 + 2];
    int etot = e0 + e1 + e2;
    bool overflow = (e0 > EMAX3) || (e1 > EMAX3) || (e2 > EMAX3);

    if (etot == 0) {
        for (int i = tid; i < NN; i += 256) sgid[i] = i;
        if (tid == 0) s_ng = NN;
        __syncthreads();
    } else {
        for (int i = tid; i < NN * 8; i += 256) (&adj[0][0])[i] = 0u;
        __syncthreads();
        if (!overflow) {
            #pragma unroll
            for (int q = 0; q < 3; q++) {
                int ec = (q == 0) ? e0 : (q == 1) ? e1 : e2;
                const int* el = &g_edges[(b * 3 + q) * EMAX3];
                for (int e = tid; e < ec; e += 256) {
                    int pk = el[e];
                    int i = pk >> 8, j = pk & 255;
                    if (j < NN && (1.0f - simp[i]) > 0.5f) {
                        atomicOr(&adj[i][j >> 5], 1u << (j & 31));
                        s_any = 1;
                    }
                }
            }
        } else {
            const float* simb = sim_in + (size_t)b * NN * NN;
            for (int idx = tid; idx < NN * NN; idx += 256) {
                int i = idx / NN, j = idx - i * NN;
                float sv = simb[idx];
                if (sv > 0.9f && (1.0f - simp[i]) > 0.5f) {
                    atomicOr(&adj[i][j >> 5], 1u << (j & 31));
                    s_any = 1;
                }
            }
        }
        __syncthreads();

        if (s_any == 0) {
            for (int i = tid; i < NN; i += 256) sgid[i] = i;
            if (tid == 0) s_ng = NN;
            __syncthreads();
        } else {
            for (int r = 0; r < NN; r++) {
                if ((assigned[r >> 5] >> (r & 31)) & 1u) continue;
                if (tid < 8) reach[tid] = (tid == (r >> 5)) ? (1u << (r & 31)) : 0u;
                __syncthreads();
                while (true) {
                    if (tid < 8) nxt[tid] = 0u;
                    if (tid == 0) s_changed = 0;
                    __syncthreads();
                    for (int i = tid; i < NN; i += 256) {
                        if ((reach[i >> 5] >> (i & 31)) & 1u) {
                            #pragma unroll
                            for (int w = 0; w < 7; w++) {
                                unsigned vv = adj[i][w];
                                if (vv) atomicOr(&nxt[w], vv);
                            }
                        }
                    }
                    __syncthreads();
                    if (tid < 8) {
                        unsigned nv = reach[tid] | (nxt[tid] & ~assigned[tid]);
                        if (nv != reach[tid]) s_changed = 1;
                        nxt[tid] = nv;
                    }
                    __syncthreads();
                    if (tid < 8) reach[tid] = nxt[tid];
                    __syncthreads();
                    if (!s_changed) break;
                }
                int gid = s_ng;
                for (int i = tid; i < NN; i += 256)
                    if ((reach[i >> 5] >> (i & 31)) & 1u) sgid[i] = gid;
                if (tid < 8) assigned[tid] |= reach[tid];
                __syncthreads();
                if (tid == 0) s_ng = gid + 1;
                __syncthreads();
            }
        }
    }

    // ---- weights + CSR ----
    for (int i = tid; i < NN; i += 256) atomicAdd(&denom[sgid[i]], simp[i]);
    __syncthreads();
    for (int i = tid; i < NN; i += 256) {
        g_w[b * NN + i] = simp[i] / denom[sgid[i]];
        if (out_gids) out_gids[b * NN + i] = (float)sgid[i];
        atomicAdd(&cnt[sgid[i]], 1);
    }
    __syncthreads();
    if (tid == 0) {
        off[0] = 0;
        for (int g = 0; g < NN; g++) off[g + 1] = off[g] + cnt[g];
    }
    __syncthreads();
    for (int g = tid; g < NN; g += 256) cur[g] = off[g];
    for (int g = tid; g < NN + 1; g += 256) g_goff[b * (NN + 1) + g] = off[g];
    __syncthreads();
    for (int i = tid; i < NN; i += 256) {
        int g = sgid[i];
        int pos = atomicAdd(&cur[g], 1);
        g_members[b * NN + pos] = i;
    }
}

// ---------------- kernel 3: merged tokens (CSR gather, float4) ----------------
__global__ void __launch_bounds__(192)
merge_kernel(const float* __restrict__ tok, float* __restrict__ out) {
    int b = blockIdx.y, g = blockIdx.x, tid = threadIdx.x;
    int o0 = g_goff[b * (NN + 1) + g];
    int o1 = g_goff[b * (NN + 1) + g + 1];
    float4 a = make_float4(0.f, 0.f, 0.f, 0.f);
    const float4* tokb = (const float4*)(tok + (size_t)b * NN * DD);
    for (int k = o0; k < o1; k++) {
        int i = g_members[b * NN + k];
        float wv = g_w[b * NN + i];
        float4 v = tokb[(size_t)i * (DD / 4) + tid];
        a.x += v.x * wv; a.y += v.y * wv; a.z += v.z * wv; a.w += v.w * wv;
    }
    ((float4*)out)[((size_t)b * NN + g) * (DD / 4) + tid] = a;
}

// ---------------- launch ------------------------------------------------------
extern "C" void kernel_launch(void* const* d_in, const int* in_sizes, int n_in,
                              void* d_out, int out_size) {
    const float* tokens = (const float*)d_in[0];
    const float* motion = (const float*)d_in[1];
    const float* sal    = (const float*)d_in[2];
    float* out = (float*)d_out;

    const long long SZ_M = (long long)BB * NN * DD;   // 19267584
    const long long SZ_S = (long long)BB * NN * NN;   //  4917248
    const long long SZ_I = (long long)BB * NN;        //    25088
    long long osz = (long long)out_size;

    float* out_sim  = (osz >= SZ_M + SZ_S)            ? out + SZ_M               : nullptr;
    float* out_imp  = (osz >= SZ_M + SZ_S + SZ_I)     ? out + SZ_M + SZ_S        : nullptr;
    float* out_gids = (osz >= SZ_M + SZ_S + 2 * SZ_I) ? out + SZ_M + SZ_S + SZ_I : nullptr;

    sim_kernel<<<dim3(3, BB), 256>>>(tokens, out_sim);
    group_kernel<<<BB, 256>>>(motion, sal, out_sim, out_imp, out_gids);
    merge_kernel<<<dim3(NN, BB), 192>>>(tokens, out);
}